// round 1
// baseline (speedup 1.0000x reference)
#include <cuda_runtime.h>
#include <math.h>

// Problem constants (fixed by the reference)
#define T_LEN    4096
#define NBLK     8192
#define NP       (NBLK / 2)          // 4096 n-pairs (float4 granularity)
#define C_CHUNKS 128
#define L_CHUNK  (T_LEN / C_CHUNKS)  // 32
#define NT       256
#define TILES    (NP / NT)           // 16

// Scratch: chunk aggregates and chunk carries, [c][np] as float4 (h0.re,h0.im,h1.re,h1.im)
__device__ float4 g_agg[C_CHUNKS * NP];
__device__ float4 g_carry[C_CHUNKS * NP];

// w = r*cos(a) - i*r*sin(a), with a = (tanh(ar)+1)/2*pi, r = (tanh(rr)+1)/2
__device__ __forceinline__ void make_w(float araw, float rraw, float& wr, float& wi) {
    float a = (tanhf(araw) + 1.0f) * 0.5f * 3.14159265358979f;
    float r = (tanhf(rraw) + 1.0f) * 0.5f;
    float s, c;
    sincosf(a, &s, &c);
    wr = r * c;
    wi = -r * s;
}

// h = w*h + z (complex)
__device__ __forceinline__ void cmad(float wr, float wi, float& hr, float& hi,
                                     float zr, float zi) {
    float nr = fmaf(wr, hr, fmaf(-wi, hi, zr));
    float ni = fmaf(wr, hi, fmaf(wi, hr, zi));
    hr = nr; hi = ni;
}

// ---------------- Kernel 1: per-chunk local aggregates ----------------
__global__ void __launch_bounds__(NT) k_agg(const float4* __restrict__ x,
                                            const float2* __restrict__ ang,
                                            const float2* __restrict__ ret) {
    const int np = blockIdx.x * NT + threadIdx.x;   // n-pair index
    const int c  = blockIdx.y;

    float2 a2 = ang[np];
    float2 r2 = ret[np];
    float w0r, w0i, w1r, w1i;
    make_w(a2.x, r2.x, w0r, w0i);
    make_w(a2.y, r2.y, w1r, w1i);

    float h0r = 0.f, h0i = 0.f, h1r = 0.f, h1i = 0.f;
    int base = c * L_CHUNK * NP + np;

#pragma unroll 8
    for (int k = 0; k < L_CHUNK; k++) {
        float4 v = x[base + k * NP];
        cmad(w0r, w0i, h0r, h0i, v.x, v.y);
        cmad(w1r, w1i, h1r, h1i, v.z, v.w);
    }
    g_agg[c * NP + np] = make_float4(h0r, h0i, h1r, h1i);
}

// ---------------- Kernel 2: sequential scan over chunk aggregates ----------------
// carry[c] = state at end of chunk c-1 (exclusive); combine: h = w^L * h + A(c)
__global__ void __launch_bounds__(NT) k_scan_chunks(const float2* __restrict__ ang,
                                                    const float2* __restrict__ ret) {
    const int np = blockIdx.x * NT + threadIdx.x;

    float2 a2 = ang[np];
    float2 r2 = ret[np];
    float w0r, w0i, w1r, w1i;
    make_w(a2.x, r2.x, w0r, w0i);
    make_w(a2.y, r2.y, w1r, w1i);

    // w^L via repeated squaring (L = 32 = 2^5)
    float l0r = w0r, l0i = w0i, l1r = w1r, l1i = w1i;
#pragma unroll
    for (int q = 0; q < 5; q++) {
        float n0r = l0r * l0r - l0i * l0i, n0i = 2.f * l0r * l0i;
        float n1r = l1r * l1r - l1i * l1i, n1i = 2.f * l1r * l1i;
        l0r = n0r; l0i = n0i; l1r = n1r; l1i = n1i;
    }

    float h0r = 0.f, h0i = 0.f, h1r = 0.f, h1i = 0.f;
#pragma unroll 1
    for (int cb = 0; cb < C_CHUNKS; cb += 8) {
        float4 v[8];
#pragma unroll
        for (int j = 0; j < 8; j++) v[j] = g_agg[(cb + j) * NP + np];
#pragma unroll
        for (int j = 0; j < 8; j++) {
            g_carry[(cb + j) * NP + np] = make_float4(h0r, h0i, h1r, h1i);
            cmad(l0r, l0i, h0r, h0i, v[j].x, v[j].y);
            cmad(l1r, l1i, h1r, h1i, v[j].z, v[j].w);
        }
    }
}

// ---------------- Kernel 3: final scan per chunk, writes outputs ----------------
__global__ void __launch_bounds__(NT) k_out(const float4* __restrict__ x,
                                            const float2* __restrict__ ang,
                                            const float2* __restrict__ ret,
                                            float4* __restrict__ y) {
    const int np = blockIdx.x * NT + threadIdx.x;
    const int c  = blockIdx.y;

    float2 a2 = ang[np];
    float2 r2 = ret[np];
    float w0r, w0i, w1r, w1i;
    make_w(a2.x, r2.x, w0r, w0i);
    make_w(a2.y, r2.y, w1r, w1i);

    float4 cv = g_carry[c * NP + np];
    float h0r = cv.x, h0i = cv.y, h1r = cv.z, h1i = cv.w;
    int base = c * L_CHUNK * NP + np;

#pragma unroll 8
    for (int k = 0; k < L_CHUNK; k++) {
        float4 v = x[base + k * NP];
        cmad(w0r, w0i, h0r, h0i, v.x, v.y);
        cmad(w1r, w1i, h1r, h1i, v.z, v.w);
        y[base + k * NP] = make_float4(h0r, h0i, h1r, h1i);
    }
}

extern "C" void kernel_launch(void* const* d_in, const int* in_sizes, int n_in,
                              void* d_out, int out_size) {
    const float4* x   = (const float4*)d_in[0];     // (T, N, 2) fp32
    const float2* ang = (const float2*)d_in[1];     // (N,)
    const float2* ret = (const float2*)d_in[2];     // (N,)
    float4* y = (float4*)d_out;                     // (T, N, 2) fp32

    dim3 grid(TILES, C_CHUNKS);
    k_agg<<<grid, NT>>>(x, ang, ret);
    k_scan_chunks<<<TILES, NT>>>(ang, ret);
    k_out<<<grid, NT>>>(x, ang, ret, y);
}

// round 2
// speedup vs baseline: 1.1606x; 1.1606x over previous
#include <cuda_runtime.h>
#include <math.h>

// Problem constants (fixed by the reference)
#define T_LEN   4096
#define NBLK    8192
#define NP      (NBLK / 2)           // 4096 n-pairs (float4 granularity)
#define CCH     128                  // time chunks
#define LCH     (T_LEN / CCH)        // 32 steps per chunk
#define NT      256
#define TILES   (NP / NT)            // 16 np-tiles
#define NBLOCKS (CCH * TILES)        // 2048

// Scratch: per-(chunk,np) aggregates and inclusive prefixes + per-block flags
__device__ float4 g_agg [CCH * NP];
__device__ float4 g_pref[CCH * NP];
__device__ int    g_flag[NBLOCKS];   // 0 = none, 1 = aggregate ready, 2 = prefix ready

// w = r*cos(a) - i*r*sin(a), with a = (tanh(ar)+1)/2*pi, r = (tanh(rr)+1)/2
__device__ __forceinline__ void make_w(float araw, float rraw, float& wr, float& wi) {
    float a = (tanhf(araw) + 1.0f) * 0.5f * 3.14159265358979f;
    float r = (tanhf(rraw) + 1.0f) * 0.5f;
    float s, c;
    sincosf(a, &s, &c);
    wr = r * c;
    wi = -r * s;
}

// h = w*h + z (complex)
__device__ __forceinline__ void cmad(float wr, float wi, float& hr, float& hi,
                                     float zr, float zi) {
    float nr = fmaf(wr, hr, fmaf(-wi, hi, zr));
    float ni = fmaf(wr, hi, fmaf(wi, hr, zi));
    hr = nr; hi = ni;
}

// (ar,ai) *= (br,bi)
__device__ __forceinline__ void cmul(float& ar, float& ai, float br, float bi) {
    float nr = ar * br - ai * bi;
    float ni = ar * bi + ai * br;
    ar = nr; ai = ni;
}

__global__ void k_reset() {
    int i = blockIdx.x * blockDim.x + threadIdx.x;
    if (i < NBLOCKS) g_flag[i] = 0;
}

__global__ void __launch_bounds__(NT, 1)
k_scan(const float4* __restrict__ x,
       const float2* __restrict__ ang,
       const float2* __restrict__ ret,
       float4* __restrict__ y)
{
    const int bid  = blockIdx.x;
    const int tile = bid & (TILES - 1);    // predecessors of (tile,c) have lower bid
    const int c    = bid >> 4;
    const int np   = tile * NT + threadIdx.x;

    // Per-block operator (complex w per channel)
    float2 a2 = ang[np];
    float2 r2 = ret[np];
    float w0r, w0i, w1r, w1i;
    make_w(a2.x, r2.x, w0r, w0i);
    make_w(a2.y, r2.y, w1r, w1i);

    // Stage the chunk slab in registers (single DRAM read of x)
    float4 v[LCH];
    const int base = c * LCH * NP + np;
#pragma unroll
    for (int k = 0; k < LCH; k++) v[k] = x[base + k * NP];

    // Local aggregate A = scan of this chunk from zero state
    float A0r = 0.f, A0i = 0.f, A1r = 0.f, A1i = 0.f;
#pragma unroll
    for (int k = 0; k < LCH; k++) {
        cmad(w0r, w0i, A0r, A0i, v[k].x, v[k].y);
        cmad(w1r, w1i, A1r, A1i, v[k].z, v[k].w);
    }

    const int sidx = c * NP + np;

    // Publish aggregate early (not needed for first/last chunk's successors)
    if (c > 0 && c < CCH - 1) {
        g_agg[sidx] = make_float4(A0r, A0i, A1r, A1i);
        __threadfence();
        __syncthreads();
        if (threadIdx.x == 0) atomicExch(&g_flag[bid], 1);
    }

    // wL = w^LCH via 5 complex squarings (LCH = 32)
    float L0r = w0r, L0i = w0i, L1r = w1r, L1i = w1i;
#pragma unroll
    for (int q = 0; q < 5; q++) {
        cmul(L0r, L0i, L0r, L0i);
        cmul(L1r, L1i, L1r, L1i);
    }

    // Decoupled lookback: exclusive prefix P = state at end of chunk c-1
    float P0r = 0.f, P0i = 0.f, P1r = 0.f, P1i = 0.f;
    if (c > 0) {
        float m0r = 1.f, m0i = 0.f, m1r = 1.f, m1i = 0.f;
        volatile int* vflag = g_flag;
        int j = c - 1;
        while (j >= 0) {
            int f = vflag[j * TILES + tile];
            if (f == 0) {
                __nanosleep(40);
                continue;
            }
            __threadfence();
            const float4* src = (f == 2) ? &g_pref[j * NP + np] : &g_agg[j * NP + np];
            float4 pv = __ldcg(src);
            // P += m * pv   (complex, both channels)
            P0r += m0r * pv.x - m0i * pv.y;  P0i += m0r * pv.y + m0i * pv.x;
            P1r += m1r * pv.z - m1i * pv.w;  P1i += m1r * pv.w + m1i * pv.z;
            if (f == 2) break;
            cmul(m0r, m0i, L0r, L0i);
            cmul(m1r, m1i, L1r, L1i);
            j--;
        }
    }

    // Publish inclusive prefix I = A + wL * P (unblocks successors before we write y)
    if (c < CCH - 1) {
        float I0r = A0r + (L0r * P0r - L0i * P0i);
        float I0i = A0i + (L0r * P0i + L0i * P0r);
        float I1r = A1r + (L1r * P1r - L1i * P1i);
        float I1i = A1i + (L1r * P1i + L1i * P1r);
        g_pref[sidx] = make_float4(I0r, I0i, I1r, I1i);
        __threadfence();
        __syncthreads();
        if (threadIdx.x == 0) atomicExch(&g_flag[bid], 2);
    }

    // Output phase: replay staged slab from the exclusive prefix
    float h0r = P0r, h0i = P0i, h1r = P1r, h1i = P1i;
#pragma unroll
    for (int k = 0; k < LCH; k++) {
        cmad(w0r, w0i, h0r, h0i, v[k].x, v[k].y);
        cmad(w1r, w1i, h1r, h1i, v[k].z, v[k].w);
        y[base + k * NP] = make_float4(h0r, h0i, h1r, h1i);
    }
}

extern "C" void kernel_launch(void* const* d_in, const int* in_sizes, int n_in,
                              void* d_out, int out_size) {
    const float4* x   = (const float4*)d_in[0];   // (T, N, 2) fp32
    const float2* ang = (const float2*)d_in[1];   // (N,)
    const float2* ret = (const float2*)d_in[2];   // (N,)
    float4* y = (float4*)d_out;

    k_reset<<<(NBLOCKS + 511) / 512, 512>>>();
    k_scan<<<NBLOCKS, NT>>>(x, ang, ret, y);
}